// round 5
// baseline (speedup 1.0000x reference)
#include <cuda_runtime.h>
#include <math.h>

// Problem constants (fixed by reference)
#define B_   8
#define T_   4096
#define D_   64
#define R_   64
#define BT_  (B_ * T_)           // 32768 tokens
#define STRENGTH 0.1f
#define PHI_SCALE 0.17677669529663689f   // sqrt(2/64)

// Scratch (static device globals — allocation-free)
__device__ float g_phi[BT_ * R_];          // 8 MB
__device__ float g_part[512 * R_];         // per-block phi_sum partials (512 blocks)
__device__ float g_phisum[B_ * R_];        // 2 KB
__device__ float g_grav[BT_];              // 128 KB

// ---------------------------------------------------------------------------
// K1: per-token phi + mass, per-block partial phi_sum.
// grid = 512 blocks (64 per batch), 256 threads. Block handles 64 tokens.
// Organization: 4 subgroups of 64 threads; each subgroup processes 4 tokens
// at a time (weight LDS amortized over the 4 tokens).
// ---------------------------------------------------------------------------
__global__ __launch_bounds__(256, 4)
void k1_phi_mass(const float* __restrict__ coords,
                 const float* __restrict__ w1, const float* __restrict__ b1,
                 const float* __restrict__ w2, const float* __restrict__ b2,
                 const float* __restrict__ W,  const float* __restrict__ b)
{
    __shared__ float Wsh[D_ * R_];     // Wsh[d*64 + r] = W[d][r]
    __shared__ float Hsh[D_ * D_];     // Hsh[d*64 + j] = w1[j][d]  (transposed)
    __shared__ float csh[4][4][D_];    // [subgroup][token-in-quad][d]
    __shared__ float redsh[8][4];      // per-warp mass partials
    __shared__ float psh[4][R_];       // cross-subgroup phi_sum partials

    const int tid  = threadIdx.x;
    const int sg   = tid >> 6;         // subgroup 0..3
    const int r    = tid & 63;         // output index within subgroup
    const int wid  = tid >> 5;         // warp 0..7
    const int lane = tid & 31;

    const int batch  = blockIdx.x >> 6;
    const int chunk  = blockIdx.x & 63;
    const int tokBase = batch * T_ + chunk * 64;

    // Stage weights (W direct; w1 transposed so inner reads are conflict-free)
    for (int i = tid; i < D_ * R_; i += 256) Wsh[i] = W[i];
    for (int i = tid; i < D_ * D_; i += 256) {
        int j = i >> 6, d = i & 63;
        Hsh[d * 64 + j] = w1[i];       // w1 row-major [j][d]
    }
    const float bv  = b[r];
    const float b1v = b1[r];
    const float w2v = w2[r];
    const float b2v = b2[0];
    __syncthreads();

    float accPS = 0.0f;                // local phi_sum contribution for this r

    #pragma unroll 1
    for (int q = 0; q < 4; ++q) {
        const int t0 = tokBase + sg * 16 + q * 4;   // first of 4 tokens

        // load 4 tokens' coords (coalesced per token)
        #pragma unroll
        for (int s = 0; s < 4; ++s)
            csh[sg][s][r] = coords[(size_t)(t0 + s) * D_ + r];
        __syncthreads();

        float accA[4] = {bv, bv, bv, bv};
        float accH[4] = {b1v, b1v, b1v, b1v};

        #pragma unroll
        for (int dd = 0; dd < 16; ++dd) {
            float4 c0 = *(const float4*)&csh[sg][0][dd * 4];
            float4 c1 = *(const float4*)&csh[sg][1][dd * 4];
            float4 c2 = *(const float4*)&csh[sg][2][dd * 4];
            float4 c3 = *(const float4*)&csh[sg][3][dd * 4];
            const float cx[4][4] = {{c0.x, c0.y, c0.z, c0.w},
                                    {c1.x, c1.y, c1.z, c1.w},
                                    {c2.x, c2.y, c2.z, c2.w},
                                    {c3.x, c3.y, c3.z, c3.w}};
            #pragma unroll
            for (int k = 0; k < 4; ++k) {
                const int d = dd * 4 + k;
                const float wv = Wsh[d * 64 + r];
                const float hv = Hsh[d * 64 + r];
                #pragma unroll
                for (int s = 0; s < 4; ++s) {
                    accA[s] = fmaf(cx[s][k], wv, accA[s]);
                    accH[s] = fmaf(cx[s][k], hv, accH[s]);
                }
            }
        }

        // phi for this r, these 4 tokens
        float phi[4];
        #pragma unroll
        for (int s = 0; s < 4; ++s) {
            phi[s] = PHI_SCALE * cosf(accA[s]);
            g_phi[(size_t)(t0 + s) * R_ + r] = phi[s];
        }

        // mass: reduce relu(h)*w2 over the 64 threads of this subgroup
        float part[4];
        #pragma unroll
        for (int s = 0; s < 4; ++s)
            part[s] = fmaxf(accH[s], 0.0f) * w2v;
        #pragma unroll
        for (int off = 16; off > 0; off >>= 1) {
            #pragma unroll
            for (int s = 0; s < 4; ++s)
                part[s] += __shfl_down_sync(0xffffffffu, part[s], off);
        }
        if (lane == 0) {
            #pragma unroll
            for (int s = 0; s < 4; ++s) redsh[wid][s] = part[s];
        }
        __syncthreads();

        #pragma unroll
        for (int s = 0; s < 4; ++s) {
            const float x = redsh[sg * 2][s] + redsh[sg * 2 + 1][s] + b2v;
            // stable softplus
            const float mass = fmaxf(x, 0.0f) + log1pf(expf(-fabsf(x)));
            accPS = fmaf(phi[s], mass, accPS);
        }
        __syncthreads();   // redsh/csh reuse next quad
    }

    // combine subgroups (deterministic) and write per-block partial
    psh[sg][r] = accPS;
    __syncthreads();
    if (sg == 0)
        g_part[blockIdx.x * R_ + r] = psh[0][r] + psh[1][r] + psh[2][r] + psh[3][r];
}

// ---------------------------------------------------------------------------
// K2: reduce 64 block-partials per (batch, r) in fixed order. <<<1, 512>>>
// ---------------------------------------------------------------------------
__global__ void k2_reduce_phisum()
{
    const int tid = threadIdx.x;       // 0..511
    const int batch = tid >> 6;
    const int r = tid & 63;
    float s = 0.0f;
    #pragma unroll 8
    for (int c = 0; c < 64; ++c)
        s += g_part[(batch * 64 + c) * R_ + r];
    g_phisum[tid] = s;
}

// ---------------------------------------------------------------------------
// K3: grav[tok] = sum_r phi[tok][r] * phisum[batch][r].  Warp per token.
// grid = 4096 blocks x 256 threads (8 warps)
// ---------------------------------------------------------------------------
__global__ __launch_bounds__(256)
void k3_grav()
{
    const int wid  = threadIdx.x >> 5;
    const int lane = threadIdx.x & 31;
    const int tok  = blockIdx.x * 8 + wid;
    const int batch = tok >> 12;       // T = 4096
    const float* ph = g_phi   + (size_t)tok * R_;
    const float* ps = g_phisum + batch * R_;
    float s = ph[lane] * ps[lane] + ph[lane + 32] * ps[lane + 32];
    #pragma unroll
    for (int off = 16; off > 0; off >>= 1)
        s += __shfl_down_sync(0xffffffffu, s, off);
    if (lane == 0) g_grav[tok] = s;
}

// ---------------------------------------------------------------------------
// K4: out = G, with +0.1*grav on the diagonal of each 64x64 tile.
// Block per token (32768 blocks), 256 threads, 4 float4 per thread. No syncs.
// ---------------------------------------------------------------------------
__global__ __launch_bounds__(256)
void k4_copy(const float4* __restrict__ G4, float4* __restrict__ out4)
{
    const int tok = blockIdx.x;
    const float g = STRENGTH * __ldg(&g_grav[tok]);
    const float4* src = G4  + (size_t)tok * 1024;   // 4096 floats = 1024 float4
    float4*       dst = out4 + (size_t)tok * 1024;

    #pragma unroll
    for (int i = 0; i < 4; ++i) {
        const int idx = threadIdx.x + i * 256;
        float4 v = src[idx];
        const int lin = idx << 2;
        if (((lin    ) >> 6) == ((lin    ) & 63)) v.x += g;
        if (((lin + 1) >> 6) == ((lin + 1) & 63)) v.y += g;
        if (((lin + 2) >> 6) == ((lin + 2) & 63)) v.z += g;
        if (((lin + 3) >> 6) == ((lin + 3) & 63)) v.w += g;
        dst[idx] = v;
    }
}

// ---------------------------------------------------------------------------
extern "C" void kernel_launch(void* const* d_in, const int* in_sizes, int n_in,
                              void* d_out, int out_size)
{
    const float* G      = (const float*)d_in[0];
    const float* coords = (const float*)d_in[1];
    const float* w1     = (const float*)d_in[2];
    const float* b1     = (const float*)d_in[3];
    const float* w2     = (const float*)d_in[4];
    const float* b2     = (const float*)d_in[5];
    const float* W      = (const float*)d_in[6];
    const float* b      = (const float*)d_in[7];
    float* out = (float*)d_out;

    k1_phi_mass<<<512, 256>>>(coords, w1, b1, w2, b2, W, b);
    k2_reduce_phisum<<<1, 512>>>();
    k3_grav<<<4096, 256>>>();
    k4_copy<<<BT_, 256>>>((const float4*)G, (float4*)out);
}

// round 6
// speedup vs baseline: 1.0097x; 1.0097x over previous
#include <cuda_runtime.h>
#include <math.h>

// Problem constants (fixed by reference)
#define B_   8
#define T_   4096
#define D_   64
#define R_   64
#define BT_  (B_ * T_)           // 32768 tokens
#define STRENGTH 0.1f
#define PHI_SCALE 0.17677669529663689f   // sqrt(2/64)

// Scratch (static device globals — allocation-free)
__device__ float g_phi[BT_ * R_];          // 8 MB
__device__ float g_part[1024 * R_];        // per-block phi_sum partials
__device__ float g_phisum[B_ * R_];        // 2 KB

typedef unsigned long long u64;

// ---- f32x2 packed helpers (FFMA2 — only reachable via PTX) -----------------
__device__ __forceinline__ u64 pack2(float lo, float hi) {
    u64 v;
    asm("mov.b64 %0, {%1, %2};" : "=l"(v)
        : "r"(__float_as_uint(lo)), "r"(__float_as_uint(hi)));
    return v;
}
__device__ __forceinline__ u64 packdup(float x) {
    u64 v; unsigned u = __float_as_uint(x);
    asm("mov.b64 %0, {%1, %1};" : "=l"(v) : "r"(u));
    return v;
}
__device__ __forceinline__ void unpack2(u64 v, float& lo, float& hi) {
    unsigned a, b;
    asm("mov.b64 {%0, %1}, %2;" : "=r"(a), "=r"(b) : "l"(v));
    lo = __uint_as_float(a); hi = __uint_as_float(b);
}
__device__ __forceinline__ u64 ffma2(u64 a, u64 b, u64 c) {
    u64 d;
    asm("fma.rn.f32x2 %0, %1, %2, %3;" : "=l"(d) : "l"(a), "l"(b), "l"(c));
    return d;
}

// ---------------------------------------------------------------------------
// K1: phi + mass + per-block phi_sum partial, FFMA2 (f32x2) mainloop.
// 1024 blocks x 128 threads. Warp handles 8 tokens; thread owns the r-pair
// (lane, lane+32) for phi and the j-pair (lane, lane+32) for the mass net.
// ---------------------------------------------------------------------------
__global__ __launch_bounds__(128, 4)
void k1_phi_mass(const float* __restrict__ coords,
                 const float* __restrict__ w1, const float* __restrict__ b1,
                 const float* __restrict__ w2, const float* __restrict__ b2,
                 const float* __restrict__ W,  const float* __restrict__ b)
{
    __shared__ float2 Wsh2[D_ * 32];   // [d][lane] = (W[d][lane], W[d][lane+32])
    __shared__ float2 Hsh2[D_ * 32];   // [d][lane] = (w1[lane][d], w1[lane+32][d])
    __shared__ float  csh[4][8][D_];   // [warp][token][d]
    __shared__ float  psum[4][R_];

    const int tid  = threadIdx.x;
    const int wid  = tid >> 5;
    const int lane = tid & 31;
    const int tokBase = blockIdx.x * 32;

    // Stage weights pre-paired for LDS.64 reads
    for (int i = tid; i < D_ * 32; i += 128) {
        const int d = i >> 5, l = i & 31;
        Wsh2[i] = make_float2(W[d * R_ + l], W[d * R_ + l + 32]);
        Hsh2[i] = make_float2(w1[l * D_ + d], w1[(l + 32) * D_ + d]);
    }
    // Stage 32 tokens' coords (coalesced float4)
    {
        const float4* src = (const float4*)(coords + (size_t)tokBase * D_);
        float4* dstc = (float4*)&csh[0][0][0];
        for (int g = tid; g < 32 * 16; g += 128) dstc[g] = src[g];
    }

    const float bv_lo = b[lane],  bv_hi = b[lane + 32];
    const float b1_lo = b1[lane], b1_hi = b1[lane + 32];
    const float w2_lo = w2[lane], w2_hi = w2[lane + 32];
    const float b2v   = b2[0];
    __syncthreads();

    u64 accA[8], accH[8];
    {
        const u64 a0 = pack2(bv_lo, bv_hi);
        const u64 h0 = pack2(b1_lo, b1_hi);
        #pragma unroll
        for (int t = 0; t < 8; ++t) { accA[t] = a0; accH[t] = h0; }
    }

    #pragma unroll 1
    for (int dd = 0; dd < 16; ++dd) {
        float4 c4[8];
        #pragma unroll
        for (int t = 0; t < 8; ++t)
            c4[t] = *(const float4*)&csh[wid][t][dd * 4];   // broadcast LDS.128

        #pragma unroll
        for (int k4 = 0; k4 < 4; ++k4) {
            const int d = dd * 4 + k4;
            const u64 wv = *(const u64*)&Wsh2[d * 32 + lane];
            const u64 hv = *(const u64*)&Hsh2[d * 32 + lane];
            #pragma unroll
            for (int t = 0; t < 8; ++t) {
                const float c = (k4 == 0) ? c4[t].x : (k4 == 1) ? c4[t].y
                              : (k4 == 2) ? c4[t].z : c4[t].w;
                const u64 cc = packdup(c);
                accA[t] = ffma2(cc, wv, accA[t]);
                accH[t] = ffma2(cc, hv, accH[t]);
            }
        }
    }

    // Epilogue: phi, mass (softplus), phi_sum partial
    float ps_lo = 0.0f, ps_hi = 0.0f;
    const int gtok0 = tokBase + wid * 8;
    #pragma unroll 1
    for (int t = 0; t < 8; ++t) {
        float alo, ahi, hlo, hhi;
        unpack2(accA[t], alo, ahi);
        unpack2(accH[t], hlo, hhi);
        const float phi_lo = PHI_SCALE * cosf(alo);
        const float phi_hi = PHI_SCALE * cosf(ahi);
        const size_t po = (size_t)(gtok0 + t) * R_;
        g_phi[po + lane]      = phi_lo;
        g_phi[po + lane + 32] = phi_hi;

        float mp = fmaxf(hlo, 0.0f) * w2_lo + fmaxf(hhi, 0.0f) * w2_hi;
        #pragma unroll
        for (int off = 16; off > 0; off >>= 1)
            mp += __shfl_xor_sync(0xffffffffu, mp, off);
        const float x = mp + b2v;
        const float mass = fmaxf(x, 0.0f) + log1pf(expf(-fabsf(x)));  // stable softplus
        ps_lo = fmaf(phi_lo, mass, ps_lo);
        ps_hi = fmaf(phi_hi, mass, ps_hi);
    }

    psum[wid][lane]      = ps_lo;
    psum[wid][lane + 32] = ps_hi;
    __syncthreads();
    if (tid < 64)
        g_part[blockIdx.x * R_ + tid] =
            psum[0][tid] + psum[1][tid] + psum[2][tid] + psum[3][tid];
}

// ---------------------------------------------------------------------------
// K2: reduce 128 block-partials per (batch, r) in fixed order. <<<8, 64>>>
// ---------------------------------------------------------------------------
__global__ void k2_reduce_phisum()
{
    const int batch = blockIdx.x;
    const int r = threadIdx.x;
    float s = 0.0f;
    #pragma unroll 8
    for (int c = 0; c < 128; ++c)
        s += g_part[(batch * 128 + c) * R_ + r];
    g_phisum[batch * R_ + r] = s;
}

// ---------------------------------------------------------------------------
// K4: grav (warp 0, fused old K3) + streaming copy of G with diagonal add.
// Block per token (32768 blocks), 256 threads, batched 4x LDG.128 then STG.
// ---------------------------------------------------------------------------
__global__ __launch_bounds__(256)
void k4_copy(const float4* __restrict__ G4, float4* __restrict__ out4)
{
    const int tok = blockIdx.x;
    __shared__ float gsh;

    if (threadIdx.x < 32) {
        const int lane = threadIdx.x;
        const int batch = tok >> 12;                 // T = 4096
        const float* ph = g_phi    + (size_t)tok * R_;
        const float* ps = g_phisum + batch * R_;
        float s = ph[lane] * ps[lane] + ph[lane + 32] * ps[lane + 32];
        #pragma unroll
        for (int off = 16; off > 0; off >>= 1)
            s += __shfl_down_sync(0xffffffffu, s, off);
        if (lane == 0) gsh = STRENGTH * s;
    }
    __syncthreads();
    const float g = gsh;

    const float4* src = G4   + (size_t)tok * 1024;   // 4096 floats
    float4*       dst = out4 + (size_t)tok * 1024;

    float4 v[4];
    #pragma unroll
    for (int i = 0; i < 4; ++i)
        v[i] = src[threadIdx.x + i * 256];           // batched loads: high MLP

    #pragma unroll
    for (int i = 0; i < 4; ++i) {
        const int idx = threadIdx.x + i * 256;
        const int lin = idx << 2;
        float4 x = v[i];
        if (((lin    ) >> 6) == ((lin    ) & 63)) x.x += g;
        if (((lin + 1) >> 6) == ((lin + 1) & 63)) x.y += g;
        if (((lin + 2) >> 6) == ((lin + 2) & 63)) x.z += g;
        if (((lin + 3) >> 6) == ((lin + 3) & 63)) x.w += g;
        dst[idx] = x;
    }
}

// ---------------------------------------------------------------------------
extern "C" void kernel_launch(void* const* d_in, const int* in_sizes, int n_in,
                              void* d_out, int out_size)
{
    const float* G      = (const float*)d_in[0];
    const float* coords = (const float*)d_in[1];
    const float* w1     = (const float*)d_in[2];
    const float* b1     = (const float*)d_in[3];
    const float* w2     = (const float*)d_in[4];
    const float* b2     = (const float*)d_in[5];
    const float* W      = (const float*)d_in[6];
    const float* b      = (const float*)d_in[7];
    float* out = (float*)d_out;

    k1_phi_mass<<<1024, 128>>>(coords, w1, b1, w2, b2, W, b);
    k2_reduce_phisum<<<8, 64>>>();
    k4_copy<<<BT_, 256>>>((const float4*)G, (float4*)out);
}

// round 7
// speedup vs baseline: 1.0240x; 1.0142x over previous
#include <cuda_runtime.h>
#include <math.h>

// Problem constants (fixed by reference)
#define B_   8
#define T_   4096
#define D_   64
#define R_   64
#define BT_  (B_ * T_)           // 32768 tokens
#define STRENGTH 0.1f
#define PHI_SCALE 0.17677669529663689f   // sqrt(2/64)

// Scratch (static device globals — allocation-free)
__device__ float g_phi[BT_ * R_];          // 8 MB
__device__ float g_part[1024 * R_];        // per-block phi_sum partials
__device__ float g_phisum[B_ * R_];        // 2 KB

typedef unsigned long long u64;

// ---- f32x2 packed helpers (FFMA2 — only reachable via PTX) -----------------
__device__ __forceinline__ u64 pack2(float lo, float hi) {
    u64 v;
    asm("mov.b64 %0, {%1, %2};" : "=l"(v)
        : "r"(__float_as_uint(lo)), "r"(__float_as_uint(hi)));
    return v;
}
__device__ __forceinline__ u64 packdup(float x) {
    u64 v; unsigned u = __float_as_uint(x);
    asm("mov.b64 %0, {%1, %1};" : "=l"(v) : "r"(u));
    return v;
}
__device__ __forceinline__ void unpack2(u64 v, float& lo, float& hi) {
    unsigned a, b;
    asm("mov.b64 {%0, %1}, %2;" : "=r"(a), "=r"(b) : "l"(v));
    lo = __uint_as_float(a); hi = __uint_as_float(b);
}
__device__ __forceinline__ u64 ffma2(u64 a, u64 b, u64 c) {
    u64 d;
    asm("fma.rn.f32x2 %0, %1, %2, %3;" : "=l"(d) : "l"(a), "l"(b), "l"(c));
    return d;
}

// ---------------------------------------------------------------------------
// K1: phi + mass + per-block phi_sum partial, FFMA2 (f32x2) mainloop.
// 1024 blocks x 256 threads (8 warps). Warp handles 4 tokens; thread owns the
// r-pair (lane, lane+32) for phi and the j-pair (lane, lane+32) for mass-net.
// ~50 regs, 42KB smem -> 5 blocks/SM, 62% occupancy (vs 26% last round).
// ---------------------------------------------------------------------------
__global__ __launch_bounds__(256, 5)
void k1_phi_mass(const float* __restrict__ coords,
                 const float* __restrict__ w1, const float* __restrict__ b1,
                 const float* __restrict__ w2, const float* __restrict__ b2,
                 const float* __restrict__ W,  const float* __restrict__ b)
{
    __shared__ float2 Wsh2[D_ * 32];   // [d][lane] = (W[d][lane], W[d][lane+32])
    __shared__ float2 Hsh2[D_ * 32];   // [d][lane] = (w1[lane][d], w1[lane+32][d])
    __shared__ float  csh[8][4][D_];   // [warp][token][d]  (8KB)
    __shared__ float  psum[8][R_];     // per-warp phi_sum partials (2KB)

    const int tid  = threadIdx.x;
    const int wid  = tid >> 5;         // 0..7
    const int lane = tid & 31;
    const int tokBase = blockIdx.x * 32;

    // Stage weights pre-paired for LDS.64 reads
    for (int i = tid; i < D_ * 32; i += 256) {
        const int d = i >> 5, l = i & 31;
        Wsh2[i] = make_float2(W[d * R_ + l], W[d * R_ + l + 32]);
        Hsh2[i] = make_float2(w1[l * D_ + d], w1[(l + 32) * D_ + d]);
    }
    // Stage 32 tokens' coords (coalesced float4; layout matches csh flat order)
    {
        const float4* src = (const float4*)(coords + (size_t)tokBase * D_);
        float4* dstc = (float4*)&csh[0][0][0];
        #pragma unroll
        for (int g = 0; g < 2; ++g) dstc[tid + g * 256] = src[tid + g * 256];
    }

    const float bv_lo = b[lane],  bv_hi = b[lane + 32];
    const float b1_lo = b1[lane], b1_hi = b1[lane + 32];
    const float w2_lo = w2[lane], w2_hi = w2[lane + 32];
    const float b2v   = b2[0];
    __syncthreads();

    u64 accA[4], accH[4];
    {
        const u64 a0 = pack2(bv_lo, bv_hi);
        const u64 h0 = pack2(b1_lo, b1_hi);
        #pragma unroll
        for (int t = 0; t < 4; ++t) { accA[t] = a0; accH[t] = h0; }
    }

    #pragma unroll 1
    for (int dd = 0; dd < 16; ++dd) {
        float4 c4[4];
        #pragma unroll
        for (int t = 0; t < 4; ++t)
            c4[t] = *(const float4*)&csh[wid][t][dd * 4];   // broadcast LDS.128

        #pragma unroll
        for (int k4 = 0; k4 < 4; ++k4) {
            const int d = dd * 4 + k4;
            const u64 wv = *(const u64*)&Wsh2[d * 32 + lane];
            const u64 hv = *(const u64*)&Hsh2[d * 32 + lane];
            #pragma unroll
            for (int t = 0; t < 4; ++t) {
                const float c = (k4 == 0) ? c4[t].x : (k4 == 1) ? c4[t].y
                              : (k4 == 2) ? c4[t].z : c4[t].w;
                const u64 cc = packdup(c);
                accA[t] = ffma2(cc, wv, accA[t]);
                accH[t] = ffma2(cc, hv, accH[t]);
            }
        }
    }

    // Epilogue: phi, mass (softplus), phi_sum partial
    float ps_lo = 0.0f, ps_hi = 0.0f;
    const int gtok0 = tokBase + wid * 4;
    #pragma unroll 1
    for (int t = 0; t < 4; ++t) {
        float alo, ahi, hlo, hhi;
        unpack2(accA[t], alo, ahi);
        unpack2(accH[t], hlo, hhi);
        const float phi_lo = PHI_SCALE * cosf(alo);
        const float phi_hi = PHI_SCALE * cosf(ahi);
        const size_t po = (size_t)(gtok0 + t) * R_;
        g_phi[po + lane]      = phi_lo;
        g_phi[po + lane + 32] = phi_hi;

        float mp = fmaxf(hlo, 0.0f) * w2_lo + fmaxf(hhi, 0.0f) * w2_hi;
        #pragma unroll
        for (int off = 16; off > 0; off >>= 1)
            mp += __shfl_xor_sync(0xffffffffu, mp, off);
        const float x = mp + b2v;
        const float mass = fmaxf(x, 0.0f) + log1pf(expf(-fabsf(x)));  // stable softplus
        ps_lo = fmaf(phi_lo, mass, ps_lo);
        ps_hi = fmaf(phi_hi, mass, ps_hi);
    }

    psum[wid][lane]      = ps_lo;
    psum[wid][lane + 32] = ps_hi;
    __syncthreads();
    if (tid < 64) {
        float s = 0.0f;
        #pragma unroll
        for (int w = 0; w < 8; ++w) s += psum[w][tid];
        g_part[blockIdx.x * R_ + tid] = s;
    }
}

// ---------------------------------------------------------------------------
// K2: reduce 128 block-partials per (batch, r) in fixed order. <<<8, 64>>>
// (blocks per batch = 4096 tokens / 32 tokens-per-block = 128)
// ---------------------------------------------------------------------------
__global__ void k2_reduce_phisum()
{
    const int batch = blockIdx.x;
    const int r = threadIdx.x;
    float s = 0.0f;
    #pragma unroll 8
    for (int c = 0; c < 128; ++c)
        s += g_part[(batch * 128 + c) * R_ + r];
    g_phisum[batch * R_ + r] = s;
}

// ---------------------------------------------------------------------------
// K4: grav (warp 0) + streaming copy of G with diagonal add.
// Block per token (32768 blocks), 256 threads, batched 4x LDG.128 then STG,
// with streaming cache hints (__ldcs/__stcs) to reduce L2 thrash.
// ---------------------------------------------------------------------------
__global__ __launch_bounds__(256)
void k4_copy(const float4* __restrict__ G4, float4* __restrict__ out4)
{
    const int tok = blockIdx.x;
    __shared__ float gsh;

    if (threadIdx.x < 32) {
        const int lane = threadIdx.x;
        const int batch = tok >> 12;                 // T = 4096
        const float* ph = g_phi    + (size_t)tok * R_;
        const float* ps = g_phisum + batch * R_;
        float s = ph[lane] * ps[lane] + ph[lane + 32] * ps[lane + 32];
        #pragma unroll
        for (int off = 16; off > 0; off >>= 1)
            s += __shfl_down_sync(0xffffffffu, s, off);
        if (lane == 0) gsh = STRENGTH * s;
    }
    __syncthreads();
    const float g = gsh;

    const float4* src = G4   + (size_t)tok * 1024;   // 4096 floats
    float4*       dst = out4 + (size_t)tok * 1024;

    float4 v[4];
    #pragma unroll
    for (int i = 0; i < 4; ++i)
        v[i] = __ldcs(&src[threadIdx.x + i * 256]);  // batched streaming loads

    #pragma unroll
    for (int i = 0; i < 4; ++i) {
        const int idx = threadIdx.x + i * 256;
        const int lin = idx << 2;
        float4 x = v[i];
        if (((lin    ) >> 6) == ((lin    ) & 63)) x.x += g;
        if (((lin + 1) >> 6) == ((lin + 1) & 63)) x.y += g;
        if (((lin + 2) >> 6) == ((lin + 2) & 63)) x.z += g;
        if (((lin + 3) >> 6) == ((lin + 3) & 63)) x.w += g;
        __stcs(&dst[idx], x);                        // streaming stores
    }
}

// ---------------------------------------------------------------------------
extern "C" void kernel_launch(void* const* d_in, const int* in_sizes, int n_in,
                              void* d_out, int out_size)
{
    const float* G      = (const float*)d_in[0];
    const float* coords = (const float*)d_in[1];
    const float* w1     = (const float*)d_in[2];
    const float* b1     = (const float*)d_in[3];
    const float* w2     = (const float*)d_in[4];
    const float* b2     = (const float*)d_in[5];
    const float* W      = (const float*)d_in[6];
    const float* b      = (const float*)d_in[7];
    float* out = (float*)d_out;

    k1_phi_mass<<<1024, 256>>>(coords, w1, b1, w2, b2, W, b);
    k2_reduce_phisum<<<8, 64>>>();
    k4_copy<<<BT_, 256>>>((const float4*)G, (float4*)out);
}